// round 6
// baseline (speedup 1.0000x reference)
#include <cuda_runtime.h>

#define EMB    64
#define NIMG   4096
#define WRUN   64          // reflections per warp (2 per step, 32 steps)
#define CH     8           // steps per software-pipelined chunk

// Scratch (allocation-free rule: __device__ globals)
__device__ float g_num[NIMG];
__device__ float g_den[NIMG];
__device__ float g_rimg[NIMG];
__device__ float g_u[EMB];
__device__ float g_c;

// ---------------------------------------------------------------------------
// Kernel P: zero accumulators (must happen inside every captured replay),
// precompute u = w_value @ w_out and c = b_value . w_out
// ---------------------------------------------------------------------------
__global__ void prep_kernel(const float* __restrict__ w_value,
                            const float* __restrict__ w_out,
                            const float* __restrict__ b_value) {
    int t = blockIdx.x * blockDim.x + threadIdx.x;
    if (t < NIMG) { g_num[t] = 0.0f; g_den[t] = 0.0f; }
    if (t < EMB) {
        float s = 0.0f;
        #pragma unroll
        for (int h = 0; h < EMB; ++h)
            s = fmaf(w_value[t * EMB + h], w_out[h], s);
        g_u[t] = s;
    }
    if (t == 0) {
        float s = 0.0f;
        #pragma unroll
        for (int h = 0; h < EMB; ++h)
            s = fmaf(b_value[h], w_out[h], s);
        g_c = s;
    }
}

// ---------------------------------------------------------------------------
// Kernel A: streaming pass, half-warp-per-reflection.
// Each LDG.128 across the warp is 512B fully contiguous (4 cache lines) ->
// minimal L1tex wavefronts. 16-lane shfl reduction produces (s, v) in the
// two leader lanes (0 and 16), which register-accumulate sorted id-runs and
// flush to global atomics only on segment change.
// ---------------------------------------------------------------------------
__global__ __launch_bounds__(256)
void main_pass(const float4* __restrict__ emb4,
               const int*    __restrict__ ids,
               const float*  __restrict__ w_attn,
               int B) {
    const int  lane = threadIdx.x & 31;
    const int  half = lane >> 4;               // which reflection of the pair
    const int  c    = lane & 15;               // float4 component within refl
    const bool leader = (c == 0);              // lanes 0 and 16

    const long warp  = (long)((blockIdx.x * (long)blockDim.x + threadIdx.x) >> 5);
    const long wbase = warp * WRUN;
    if (wbase >= (long)B) return;              // warp-uniform

    const float4* wa4 = (const float4*)w_attn;
    const float4* uu4 = (const float4*)g_u;
    const float4 wa = wa4[c];
    const float4 uu = uu4[c];

    float accD = 0.0f, accN = 0.0f;
    int cur = -1;

    const int steps = WRUN / 2;                // 2 reflections per step
    for (int j0 = 0; j0 < steps; j0 += CH) {
        // ---- batched loads: CH independent 512B warp-coalesced LDGs ----
        float4 e[CH];
        #pragma unroll
        for (int t = 0; t < CH; ++t) {
            long r = wbase + 2L * (j0 + t) + half;
            long rr = (r < (long)B) ? r : 0;
            e[t] = __ldg(emb4 + rr * (EMB / 4) + c);
        }
        // leader prefetches its CH segment ids (adds MLP on the id stream)
        int idb[CH];
        if (leader) {
            #pragma unroll
            for (int t = 0; t < CH; ++t) {
                long r = wbase + 2L * (j0 + t) + half;
                idb[t] = __ldg(ids + ((r < (long)B) ? r : (long)(B - 1)));
            }
        }
        // ---- compute + reduce + accumulate ----
        #pragma unroll
        for (int t = 0; t < CH; ++t) {
            float s = e[t].x * wa.x + e[t].y * wa.y + e[t].z * wa.z + e[t].w * wa.w;
            float v = e[t].x * uu.x + e[t].y * uu.y + e[t].z * uu.z + e[t].w * uu.w;
            #pragma unroll
            for (int m = 1; m <= 8; m <<= 1) {
                s += __shfl_xor_sync(0xFFFFFFFFu, s, m);
                v += __shfl_xor_sync(0xFFFFFFFFu, v, m);
            }
            long r = wbase + 2L * (j0 + t) + half;
            if (leader && r < (long)B) {
                int id = idb[t];
                float ex = __expf(s);
                if (id != cur) {
                    if (cur >= 0) {
                        atomicAdd(&g_den[cur], accD);
                        atomicAdd(&g_num[cur], accN);
                    }
                    cur = id; accD = 0.0f; accN = 0.0f;
                }
                accD += ex;
                accN = fmaf(ex, v, accN);
            }
        }
    }
    if (leader && cur >= 0) {
        atomicAdd(&g_den[cur], accD);
        atomicAdd(&g_num[cur], accN);
    }
}

// ---------------------------------------------------------------------------
// Kernel B: per-image result. Empty segment -> pooled = 0 -> b_out.
// ---------------------------------------------------------------------------
__global__ void finalize_images(float* __restrict__ out_img,
                                float* __restrict__ out_ids,
                                const float* __restrict__ b_out,
                                int write_img, int write_ids) {
    int n = blockIdx.x * blockDim.x + threadIdx.x;
    if (n >= NIMG) return;
    float d  = g_den[n];
    float bo = b_out[0];
    float r  = (d > 0.0f) ? (g_num[n] / d + g_c + bo) : bo;
    g_rimg[n] = r;
    if (write_img) out_img[n] = r;
    if (write_ids) out_ids[n] = (float)n;
}

// ---------------------------------------------------------------------------
// Kernel C: broadcast r_images back to reflections.
// 4 warp-stride-coalesced int4 per thread for MLP=4 on the load chain.
// ---------------------------------------------------------------------------
__global__ __launch_bounds__(256)
void gather_reflections(const int4* __restrict__ ids4,
                        float4* __restrict__ out4,
                        int B4) {
    int base = blockIdx.x * (blockDim.x * 4) + threadIdx.x;
    int4 id[4];
    bool ok[4];
    #pragma unroll
    for (int t = 0; t < 4; ++t) {
        int i = base + t * blockDim.x;
        ok[t] = (i < B4);
        id[t] = ok[t] ? __ldg(ids4 + i) : make_int4(0, 0, 0, 0);
    }
    #pragma unroll
    for (int t = 0; t < 4; ++t) {
        if (ok[t]) {
            float4 o = make_float4(g_rimg[id[t].x], g_rimg[id[t].y],
                                   g_rimg[id[t].z], g_rimg[id[t].w]);
            out4[base + t * blockDim.x] = o;
        }
    }
}

// scalar tail (only launched if B % 4 != 0; B = 1M in practice)
__global__ void gather_tail(const int* __restrict__ ids,
                            float* __restrict__ out,
                            int start, int B) {
    int i = start + blockIdx.x * blockDim.x + threadIdx.x;
    if (i < B) out[i] = g_rimg[ids[i]];
}

// ---------------------------------------------------------------------------
extern "C" void kernel_launch(void* const* d_in, const int* in_sizes, int n_in,
                              void* d_out, int out_size) {
    // metadata order: emb, img_ids, w_attn, b_attn, w_value, b_value, w_out, b_out
    const float* emb     = (const float*)d_in[0];
    const int*   ids     = (const int*)  d_in[1];
    const float* w_attn  = (const float*)d_in[2];
    // d_in[3] = b_attn: cancels in the per-segment softmax, unused.
    const float* w_value = (const float*)d_in[4];
    const float* b_value = (const float*)d_in[5];
    const float* w_out   = (const float*)d_in[6];
    const float* b_out   = (const float*)d_in[7];

    const int B = in_sizes[0] / EMB;
    float* out = (float*)d_out;

    // P: zero accumulators + precompute u, c
    prep_kernel<<<(NIMG + 255) / 256, 256>>>(w_value, w_out, b_value);

    // A: streaming main pass — one warp per WRUN reflections
    long warps   = ((long)B + WRUN - 1) / WRUN;
    long threads = warps * 32;
    int  blocks  = (int)((threads + 255) / 256);
    main_pass<<<blocks, 256>>>((const float4*)emb, ids, w_attn, B);

    // B: per-image finalize (+ tail outputs when harness flattens the tuple)
    int write_img = (out_size >= B + NIMG)     ? 1 : 0;
    int write_ids = (out_size >= B + 2 * NIMG) ? 1 : 0;
    finalize_images<<<(NIMG + 255) / 256, 256>>>(out + B, out + B + NIMG,
                                                 b_out, write_img, write_ids);

    // C: r_reflections = r_images[ids]
    int B4 = B / 4;
    int gblocks = (B4 + 1023) / 1024;   // 4 int4 per thread, 256 threads
    gather_reflections<<<gblocks, 256>>>((const int4*)ids, (float4*)out, B4);
    int rem = B4 * 4;
    if (rem < B)
        gather_tail<<<1, 256>>>(ids, out, rem, B);
}